// round 8
// baseline (speedup 1.0000x reference)
#include <cuda_runtime.h>
#include <math.h>

#define BN 64
#define CN 512
#define HW 784
#define HW4 196
#define NSEG 8
#define FEPS 1e-12f
#define NSWEEP 6
#define ITEMS_SWEEP (BN * NSEG)                 // 512
#define ITEMS_MAIN (NSWEEP * ITEMS_SWEEP)       // 3072
#define NITEMS (ITEMS_MAIN + BN + 1)            // 3137

// ---------------- scratch (static __device__, no allocation) ----------------
__device__ float g_Ya[NSEG * BN * HW];    // even sweeps' output (Y0, Y2, Y4 partials)
__device__ float g_Yb[NSEG * BN * HW];    // odd sweeps' output (Y1, Y3, Y5 partials)
__device__ float g_u4[BN * CN];           // z4 raw
__device__ float g_nrm2[8][BN];           // 0:||x0||^2, 1..4:||z_k||^2
__device__ float g_sc[4][BN];             // 1:||w||^2, 2:pen_b
__device__ int   g_cnt[NSWEEP][BN];       // per-(sweep,batch) completion counters
__device__ int   g_cnt6;                  // penalty completion counter
__device__ int   g_ticket;                // dynamic work ticket

// L2 evict_last policy for A loads (103MB vs 126MB L2)
__device__ __forceinline__ unsigned long long mk_policy() {
    unsigned long long pol;
    asm("createpolicy.fractional.L2::evict_last.b64 %0, 1.0;" : "=l"(pol));
    return pol;
}
__device__ __forceinline__ float4 ldg_el(const float4* p, unsigned long long pol) {
    float4 r;
    asm volatile("ld.global.nc.L2::cache_hint.v4.f32 {%0,%1,%2,%3}, [%4], %5;"
                 : "=f"(r.x), "=f"(r.y), "=f"(r.z), "=f"(r.w) : "l"(p), "l"(pol));
    return r;
}
// cross-block mutable data: bypass (possibly stale) L1
__device__ __forceinline__ float ldcg(const float* p) {
    float v;
    asm volatile("ld.global.cg.f32 %0, [%1];" : "=f"(v) : "l"(p));
    return v;
}

// ---------------- init: zero counters/accums, ||x0||^2 ----------------
__global__ void k_init0(const float* __restrict__ x0) {
    __shared__ float red[16];
    int b = blockIdx.x, t = threadIdx.x;       // 512 threads
    if (t < 8) g_nrm2[t][b] = 0.0f;
    if (t < 4) g_sc[t][b] = 0.0f;
    if (t < NSWEEP) g_cnt[t][b] = 0;
    if (b == 0 && t == 0) { g_cnt6 = 0; g_ticket = 0; }
    float v = x0[b * CN + t];
    float s = v * v;
    #pragma unroll
    for (int o = 16; o; o >>= 1) s += __shfl_xor_sync(0xffffffffu, s, o);
    if ((t & 31) == 0) red[t >> 5] = s;
    __syncthreads();
    if (t < 16) {
        s = red[t];
        #pragma unroll
        for (int o = 8; o; o >>= 1) s += __shfl_xor_sync(0xffffu, s, o);
        if (t == 0) g_nrm2[0][b] = s;
    }
}

// ---------------- persistent mega-kernel: all 6 sweeps + penalty + sum ------
__global__ void __launch_bounds__(256, 2) k_mega(
        const float4* __restrict__ A4, const float* __restrict__ x0,
        float* __restrict__ out)
{
    __shared__ float ys[HW];
    __shared__ float yw[8][HW];
    __shared__ float r1s[8];
    __shared__ float sh_bcast;
    __shared__ int sh_w;
    int t = threadIdx.x, warp = t >> 5, lane = t & 31;
    unsigned long long pol = mk_policy();

    for (;;) {
        if (t == 0) sh_w = atomicAdd(&g_ticket, 1);
        __syncthreads();
        int w = sh_w;
        if (w >= NITEMS) break;

        if (w < ITEMS_MAIN) {
            // ---------------- A-sweep item ----------------
            int sweep = w / ITEMS_SWEEP;
            int r = w - sweep * ITEMS_SWEEP;
            int b = r >> 3, seg = r & 7;

            if (sweep > 0) {
                if (t == 0) {
                    volatile int* c = &g_cnt[sweep - 1][b];
                    while (*c < NSEG) __nanosleep(64);
                    __threadfence();
                }
                __syncthreads();
            }

            const float* Yin = (sweep & 1) ? g_Ya : g_Yb;   // sweep1 reads Ya...
            float* Yout = (sweep & 1) ? g_Yb : g_Ya;

            float largest = 0.f, invu4 = 1.f;
            if (sweep >= 1 && sweep <= 4) {
                float s = 1.0f / fmaxf(sqrtf(ldcg(&g_nrm2[sweep - 1][b])), FEPS);
                for (int i = t; i < HW; i += 256) {
                    float acc = 0.f;
                    #pragma unroll
                    for (int sg = 0; sg < NSEG; sg++)
                        acc += ldcg(&Yin[(sg * BN + b) * HW + i]);
                    ys[i] = acc * s;
                }
                __syncthreads();
            } else if (sweep == 5) {
                invu4 = 1.0f / fmaxf(sqrtf(ldcg(&g_nrm2[4][b])), FEPS);
                float loc = 0.f;
                for (int i = t; i < HW; i += 256) {
                    float acc = 0.f;
                    #pragma unroll
                    for (int sg = 0; sg < NSEG; sg++)
                        acc += ldcg(&g_Ya[(sg * BN + b) * HW + i]);
                    ys[i] = acc; loc += acc * acc;
                }
                #pragma unroll
                for (int o = 16; o; o >>= 1) loc += __shfl_xor_sync(0xffffffffu, loc, o);
                if (lane == 0) r1s[warp] = loc;
                __syncthreads();
                if (t == 0) {
                    float tot = 0.f;
                    #pragma unroll
                    for (int ww = 0; ww < 8; ww++) tot += r1s[ww];
                    sh_bcast = tot;
                }
                __syncthreads();
                largest = sh_bcast * invu4 * invu4;     // ||W^T x1||^2
                for (int i = t; i < HW; i += 256) ys[i] *= invu4;
                __syncthreads();
            }

            // ---- row loop: 8 warps x 8 rows, double-buffered A pipeline ----
            const float4* ys4 = (const float4*)ys;
            bool k6 = (lane < 4);
            float4 acc[7];
            #pragma unroll
            for (int k = 0; k < 7; k++) acc[k] = make_float4(0.f, 0.f, 0.f, 0.f);
            float la1 = 0.f;
            int c0 = seg * 64 + warp * 8;
            const float4* Ar0 = A4 + (size_t)(b * CN + c0) * HW4;

            float4 cur[7], nxt[7];
            #pragma unroll
            for (int k = 0; k < 6; k++) cur[k] = ldg_el(Ar0 + k * 32 + lane, pol);
            cur[6] = k6 ? ldg_el(Ar0 + 192 + lane, pol) : make_float4(0.f, 0.f, 0.f, 0.f);

            #pragma unroll
            for (int rr = 0; rr < 8; rr++) {
                if (rr < 7) {
                    const float4* Arn = Ar0 + (size_t)(rr + 1) * HW4;
                    #pragma unroll
                    for (int k = 0; k < 6; k++) nxt[k] = ldg_el(Arn + k * 32 + lane, pol);
                    nxt[6] = k6 ? ldg_el(Arn + 192 + lane, pol) : make_float4(0.f, 0.f, 0.f, 0.f);
                }
                float z;
                if (sweep == 0) {
                    z = __ldg(&x0[b * CN + c0 + rr]);
                } else {
                    float d0 = 0.f, d1 = 0.f, d2 = 0.f, d3 = 0.f;
                    #pragma unroll
                    for (int k = 0; k < 6; k++) {
                        float4 y = ys4[k * 32 + lane];
                        d0 += cur[k].x * y.x; d1 += cur[k].y * y.y;
                        d2 += cur[k].z * y.z; d3 += cur[k].w * y.w;
                    }
                    if (k6) {
                        float4 y = ys4[192 + lane];
                        d0 += cur[6].x * y.x; d1 += cur[6].y * y.y;
                        d2 += cur[6].z * y.z; d3 += cur[6].w * y.w;
                    }
                    z = (d0 + d1) + (d2 + d3);
                    #pragma unroll
                    for (int o = 16; o; o >>= 1) z += __shfl_xor_sync(0xffffffffu, z, o);
                }
                #pragma unroll
                for (int k = 0; k < 7; k++) {
                    acc[k].x += z * cur[k].x; acc[k].y += z * cur[k].y;
                    acc[k].z += z * cur[k].z; acc[k].w += z * cur[k].w;
                }
                if (lane == 0) {
                    int c = c0 + rr;
                    if (sweep >= 1 && sweep <= 4) {
                        if (sweep == 4) g_u4[b * CN + c] = z;
                        la1 += z * z;
                    } else if (sweep == 5) {
                        float wv = z - largest * (ldcg(&g_u4[b * CN + c]) * invu4);
                        la1 += wv * wv;
                    }
                }
                if (rr < 7) {
                    #pragma unroll
                    for (int k = 0; k < 7; k++) cur[k] = nxt[k];
                }
            }

            // ---- flush Y partial + scalars, then flag completion ----
            {
                float4* yo = (float4*)yw[warp];
                #pragma unroll
                for (int k = 0; k < 6; k++) yo[k * 32 + lane] = acc[k];
                if (k6) yo[192 + lane] = acc[6];
            }
            if (lane == 0) r1s[warp] = la1;
            __syncthreads();
            {
                float* Yp = &Yout[(seg * BN + b) * HW];
                for (int i = t; i < HW; i += 256) {
                    float s = 0.f;
                    #pragma unroll
                    for (int ww = 0; ww < 8; ww++) s += yw[ww][i];
                    Yp[i] = s;
                }
            }
            if (t == 0 && sweep >= 1) {
                float s1 = 0.f;
                #pragma unroll
                for (int ww = 0; ww < 8; ww++) s1 += r1s[ww];
                if (sweep <= 4) atomicAdd(&g_nrm2[sweep][b], s1);
                else            atomicAdd(&g_sc[1][b], s1);
            }
            __syncthreads();
            if (t == 0) {
                __threadfence();
                atomicAdd(&g_cnt[sweep][b], 1);
            }
        } else if (w < ITEMS_MAIN + BN) {
            // ---------------- penalty item (one per batch) ----------------
            int b = w - ITEMS_MAIN;
            if (t == 0) {
                volatile int* c = &g_cnt[5][b];
                while (*c < NSEG) __nanosleep(64);
                __threadfence();
            }
            __syncthreads();
            float invu4 = 1.0f / fmaxf(sqrtf(ldcg(&g_nrm2[4][b])), FEPS);
            float loc = 0.f;
            for (int i = t; i < HW; i += 256) {
                float acc = 0.f;
                #pragma unroll
                for (int sg = 0; sg < NSEG; sg++)
                    acc += ldcg(&g_Ya[(sg * BN + b) * HW + i]);
                ys[i] = acc; loc += acc * acc;
            }
            #pragma unroll
            for (int o = 16; o; o >>= 1) loc += __shfl_xor_sync(0xffffffffu, loc, o);
            if (lane == 0) r1s[warp] = loc;
            __syncthreads();
            if (t == 0) {
                float tot = 0.f;
                #pragma unroll
                for (int ww = 0; ww < 8; ww++) tot += r1s[ww];
                sh_bcast = tot;
            }
            __syncthreads();
            float largest = sh_bcast * invu4 * invu4;   // bitwise == sweep5's
            float f = largest * invu4;
            float loc6 = 0.f;
            for (int i = t; i < HW; i += 256) {
                float s5 = 0.f;
                #pragma unroll
                for (int sg = 0; sg < NSEG; sg++)
                    s5 += ldcg(&g_Yb[(sg * BN + b) * HW + i]);
                float y6 = s5 - f * ys[i];              // W^T w (scale-invariant)
                loc6 += y6 * y6;
            }
            #pragma unroll
            for (int o = 16; o; o >>= 1) loc6 += __shfl_xor_sync(0xffffffffu, loc6, o);
            if (lane == 0) r1s[warp] = loc6;
            __syncthreads();
            if (t == 0) {
                float num6 = 0.f;
                #pragma unroll
                for (int ww = 0; ww < 8; ww++) num6 += r1s[ww];
                float smallest = num6 / ldcg(&g_sc[1][b]);  // ||W^T w||^2/||w||^2
                float rr = largest / smallest - 1.0f;
                g_sc[2][b] = rr * rr;
                __threadfence();
                atomicAdd(&g_cnt6, 1);
            }
        } else {
            // ---------------- final sum item ----------------
            if (t == 0) {
                volatile int* c = &g_cnt6;
                while (*c < BN) __nanosleep(64);
                __threadfence();
            }
            __syncthreads();
            float p = (t < BN) ? ldcg(&g_sc[2][t]) : 0.f;
            #pragma unroll
            for (int o = 16; o; o >>= 1) p += __shfl_xor_sync(0xffffffffu, p, o);
            if (lane == 0) r1s[warp] = p;
            __syncthreads();
            if (t == 0) out[0] = (r1s[0] + r1s[1]) / (float)BN;
        }
        __syncthreads();
    }
}

// ---------------- launch ----------------
extern "C" void kernel_launch(void* const* d_in, const int* in_sizes, int n_in,
                              void* d_out, int out_size) {
    const float* A  = (const float*)d_in[0];
    const float* x0 = (const float*)d_in[1];
    if (n_in >= 2 && in_sizes[0] < in_sizes[1]) {   // safety: A is the big one
        const float* t = A; A = x0; x0 = t;
    }
    const float4* A4 = (const float4*)A;
    float* out = (float*)d_out;
    (void)out_size;

    int nsm = 148;
    cudaDeviceGetAttribute(&nsm, cudaDevAttrMultiProcessorCount, 0);
    int grid = nsm * 2;                     // fully resident persistent grid
    if (grid > NITEMS) grid = NITEMS;

    k_init0<<<BN, CN>>>(x0);
    k_mega<<<grid, 256>>>(A4, x0, out);
}